// round 11
// baseline (speedup 1.0000x reference)
#include <cuda_runtime.h>
#include <cuda_bf16.h>
#include <cstdint>

// OctreeMaxUnpool:
//   out[(i*8 + c)*C + k] = (indices[i*C + k] == c) ? data[nempty_idx[i]*C + k] : 0
//
// FINAL (R6/R8 configuration, reproduced 3x at 182.5-183.1 us, DRAM 82.5-82.8%,
// traffic at the compulsory minimum ~1.18 GB = 1.024 GB writes + 128 MB
// indices + ~87 MB deduped gather reads):
//  - One warp per row (C=64): every STG.128 instruction writes 512 fully
//    contiguous ascending bytes; 4 stores cover the row's 2048-B span.
//  - __stcs on the write-once output (full-line-per-instruction pattern).
//  - __ldcs on the read-once indices / nempty_idx streams; __ldg on the
//    gathered data rows (~32% duplication -> keep L2-cached).
//  - Flat launch, block=256.
// Measured dead ends (do not reintroduce): partial-line store instructions
// (R2: +50% DRAM write traffic), per-warp row batching (R5: L1tex queue
// serialization), persistent grid-stride (R7: per-row dependent chain
// exposes gather latency), block=512 (R9: occupancy quantization).
// Analyzed dead ends: memset+sparse-scatter (adds RMW traffic), TMA stores
// (LTS cap path-independent), wider stores (issue not binding at 16.6%).

#define NUM_CHILDREN 8

__device__ __forceinline__ float4 child_select(int4 ix, float4 d, int c) {
    float4 o;
    o.x = (ix.x == c) ? d.x : 0.0f;
    o.y = (ix.y == c) ? d.y : 0.0f;
    o.z = (ix.z == c) ? d.z : 0.0f;
    o.w = (ix.w == c) ? d.w : 0.0f;
    return o;
}

// C = 64 fast path: one warp per row.
__global__ void __launch_bounds__(256)
octree_unpool_warprow_kernel(const float4* __restrict__ data,
                             const int4*  __restrict__ indices,
                             const int*   __restrict__ nempty_idx,
                             float4*      __restrict__ out,
                             int num)
{
    constexpr int C4 = 16;                       // float4 lanes per row
    int gtid = blockIdx.x * blockDim.x + threadIdx.x;
    int i    = gtid >> 5;                        // row = warp id
    int t    = gtid & 31;                        // lane in warp
    if (i >= num) return;

    int l = t & 15;                              // float4 lane within row
    int h = t >> 4;                              // half-warp id (0/1)

    int src = __ldcs(&nempty_idx[i]);            // read-once: evict-first
    float4 d  = __ldg(&data[(long long)src * C4 + l]);      // reused: cached
    int4   ix = __ldcs(&indices[(long long)i * C4 + l]);    // read-once

    float4* rowbase = out + (long long)i * (NUM_CHILDREN * C4);
#pragma unroll
    for (int j = 0; j < 4; j++) {
        int c = h + 2 * j;                       // child slot this thread writes
        // position within row = c*16 + l = t + 32*j  (ascending contiguous)
        __stcs(rowbase + t + 32 * j, child_select(ix, d, c));
    }
}

// Generic-C vectorized kernel (runtime C4) for C % 4 == 0 but C != 64.
__global__ void __launch_bounds__(256)
octree_unpool_vec_dyn_kernel(const float4* __restrict__ data,
                             const int4*  __restrict__ indices,
                             const int*   __restrict__ nempty_idx,
                             float4*      __restrict__ out,
                             int num, int C4)
{
    int gtid = blockIdx.x * blockDim.x + threadIdx.x;
    int i    = gtid / C4;
    int lane = gtid - i * C4;
    if (i >= num) return;

    int src = __ldcs(&nempty_idx[i]);
    float4 d  = __ldg(&data[(long long)src * C4 + lane]);
    int4   ix = __ldcs(&indices[(long long)i * C4 + lane]);

    long long base = (long long)i * (NUM_CHILDREN * C4) + lane;
#pragma unroll
    for (int c = 0; c < NUM_CHILDREN; c++) {
        out[base + (long long)c * C4] = child_select(ix, d, c);
    }
}

// Scalar fallback for arbitrary C.
__global__ void __launch_bounds__(256)
octree_unpool_scalar_kernel(const float* __restrict__ data,
                            const int*   __restrict__ indices,
                            const int*   __restrict__ nempty_idx,
                            float*       __restrict__ out,
                            int num, int C)
{
    long long gtid = (long long)blockIdx.x * blockDim.x + threadIdx.x;
    long long total = (long long)num * C;
    if (gtid >= total) return;
    int i = (int)(gtid / C);
    int k = (int)(gtid - (long long)i * C);

    int src  = __ldcs(&nempty_idx[i]);
    float dv = __ldg(&data[(long long)src * C + k]);
    int   ix = __ldcs(&indices[(long long)i * C + k]);

    long long base = ((long long)i * NUM_CHILDREN) * C + k;
#pragma unroll
    for (int c = 0; c < NUM_CHILDREN; c++) {
        out[base + (long long)c * C] = (ix == c) ? dv : 0.0f;
    }
}

extern "C" void kernel_launch(void* const* d_in, const int* in_sizes, int n_in,
                              void* d_out, int out_size)
{
    const float* data       = (const float*)d_in[0];
    const int*   indices    = (const int*)d_in[1];
    const int*   nempty_idx = (const int*)d_in[2];
    // d_in[3] = depth (unused: the gather is already expressed by nempty_idx)

    float* out = (float*)d_out;

    int num = in_sizes[2];
    int C   = (num > 0) ? (in_sizes[1] / num) : 0;

    if (num <= 0 || C <= 0) return;

    if (C == 64) {
        long long threads = (long long)num * 32;   // one warp per row
        int block = 256;
        int grid  = (int)((threads + block - 1) / block);
        octree_unpool_warprow_kernel<<<grid, block>>>(
            (const float4*)data, (const int4*)indices, nempty_idx,
            (float4*)out, num);
    } else if ((C & 3) == 0) {
        int C4 = C >> 2;
        long long threads = (long long)num * C4;
        int block = 256;
        int grid  = (int)((threads + block - 1) / block);
        octree_unpool_vec_dyn_kernel<<<grid, block>>>(
            (const float4*)data, (const int4*)indices, nempty_idx,
            (float4*)out, num, C4);
    } else {
        long long threads = (long long)num * C;
        int block = 256;
        int grid  = (int)((threads + block - 1) / block);
        octree_unpool_scalar_kernel<<<grid, block>>>(
            data, indices, nempty_idx, out, num, C);
    }
}

// round 12
// speedup vs baseline: 1.0014x; 1.0014x over previous
#include <cuda_runtime.h>
#include <cuda_bf16.h>
#include <cstdint>

// OctreeMaxUnpool:
//   out[(i*8 + c)*C + k] = (indices[i*C + k] == c) ? data[nempty_idx[i]*C + k] : 0
//
// R12 = converged-optimum kernel (R6/R8: 182.5-183.5 us, DRAM 82.3-82.8%,
// compulsory-minimum traffic ~1.18 GB) with block 256 -> 128, completing the
// block-size sweep (512 measured -1%; 256 best so far). Per-warp behavior
// identical: one warp per row; each STG.128 writes 512 fully contiguous
// ascending bytes; __stcs output; __ldcs read-once streams; __ldg cached
// gather; regs=22.
// Measured dead ends: partial-line stores (R2), row batching (R5),
// persistent grid-stride (R7), block=512 (R9).

#define NUM_CHILDREN 8

__device__ __forceinline__ float4 child_select(int4 ix, float4 d, int c) {
    float4 o;
    o.x = (ix.x == c) ? d.x : 0.0f;
    o.y = (ix.y == c) ? d.y : 0.0f;
    o.z = (ix.z == c) ? d.z : 0.0f;
    o.w = (ix.w == c) ? d.w : 0.0f;
    return o;
}

// C = 64 fast path: one warp per row.
__global__ void __launch_bounds__(128)
octree_unpool_warprow_kernel(const float4* __restrict__ data,
                             const int4*  __restrict__ indices,
                             const int*   __restrict__ nempty_idx,
                             float4*      __restrict__ out,
                             int num)
{
    constexpr int C4 = 16;                       // float4 lanes per row
    int gtid = blockIdx.x * blockDim.x + threadIdx.x;
    int i    = gtid >> 5;                        // row = warp id
    int t    = gtid & 31;                        // lane in warp
    if (i >= num) return;

    int l = t & 15;                              // float4 lane within row
    int h = t >> 4;                              // half-warp id (0/1)

    int src = __ldcs(&nempty_idx[i]);            // read-once: evict-first
    float4 d  = __ldg(&data[(long long)src * C4 + l]);      // reused: cached
    int4   ix = __ldcs(&indices[(long long)i * C4 + l]);    // read-once

    float4* rowbase = out + (long long)i * (NUM_CHILDREN * C4);
#pragma unroll
    for (int j = 0; j < 4; j++) {
        int c = h + 2 * j;                       // child slot this thread writes
        // position within row = c*16 + l = t + 32*j  (ascending contiguous)
        __stcs(rowbase + t + 32 * j, child_select(ix, d, c));
    }
}

// Generic-C vectorized kernel (runtime C4) for C % 4 == 0 but C != 64.
__global__ void __launch_bounds__(256)
octree_unpool_vec_dyn_kernel(const float4* __restrict__ data,
                             const int4*  __restrict__ indices,
                             const int*   __restrict__ nempty_idx,
                             float4*      __restrict__ out,
                             int num, int C4)
{
    int gtid = blockIdx.x * blockDim.x + threadIdx.x;
    int i    = gtid / C4;
    int lane = gtid - i * C4;
    if (i >= num) return;

    int src = __ldcs(&nempty_idx[i]);
    float4 d  = __ldg(&data[(long long)src * C4 + lane]);
    int4   ix = __ldcs(&indices[(long long)i * C4 + lane]);

    long long base = (long long)i * (NUM_CHILDREN * C4) + lane;
#pragma unroll
    for (int c = 0; c < NUM_CHILDREN; c++) {
        out[base + (long long)c * C4] = child_select(ix, d, c);
    }
}

// Scalar fallback for arbitrary C.
__global__ void __launch_bounds__(256)
octree_unpool_scalar_kernel(const float* __restrict__ data,
                            const int*   __restrict__ indices,
                            const int*   __restrict__ nempty_idx,
                            float*       __restrict__ out,
                            int num, int C)
{
    long long gtid = (long long)blockIdx.x * blockDim.x + threadIdx.x;
    long long total = (long long)num * C;
    if (gtid >= total) return;
    int i = (int)(gtid / C);
    int k = (int)(gtid - (long long)i * C);

    int src  = __ldcs(&nempty_idx[i]);
    float dv = __ldg(&data[(long long)src * C + k]);
    int   ix = __ldcs(&indices[(long long)i * C + k]);

    long long base = ((long long)i * NUM_CHILDREN) * C + k;
#pragma unroll
    for (int c = 0; c < NUM_CHILDREN; c++) {
        out[base + (long long)c * C] = (ix == c) ? dv : 0.0f;
    }
}

extern "C" void kernel_launch(void* const* d_in, const int* in_sizes, int n_in,
                              void* d_out, int out_size)
{
    const float* data       = (const float*)d_in[0];
    const int*   indices    = (const int*)d_in[1];
    const int*   nempty_idx = (const int*)d_in[2];
    // d_in[3] = depth (unused: the gather is already expressed by nempty_idx)

    float* out = (float*)d_out;

    int num = in_sizes[2];
    int C   = (num > 0) ? (in_sizes[1] / num) : 0;

    if (num <= 0 || C <= 0) return;

    if (C == 64) {
        long long threads = (long long)num * 32;   // one warp per row
        int block = 128;
        int grid  = (int)((threads + block - 1) / block);
        octree_unpool_warprow_kernel<<<grid, block>>>(
            (const float4*)data, (const int4*)indices, nempty_idx,
            (float4*)out, num);
    } else if ((C & 3) == 0) {
        int C4 = C >> 2;
        long long threads = (long long)num * C4;
        int block = 256;
        int grid  = (int)((threads + block - 1) / block);
        octree_unpool_vec_dyn_kernel<<<grid, block>>>(
            (const float4*)data, (const int4*)indices, nempty_idx,
            (float4*)out, num, C4);
    } else {
        long long threads = (long long)num * C;
        int block = 256;
        int grid  = (int)((threads + block - 1) / block);
        octree_unpool_scalar_kernel<<<grid, block>>>(
            data, indices, nempty_idx, out, num, C);
    }
}

// round 13
// speedup vs baseline: 1.0021x; 1.0007x over previous
#include <cuda_runtime.h>
#include <cuda_bf16.h>
#include <cstdint>

// OctreeMaxUnpool:
//   out[(i*8 + c)*C + k] = (indices[i*C + k] == c) ? data[nempty_idx[i]*C + k] : 0
//
// FINAL kernel (R6/R8 configuration; best across a 12-round sweep:
// 182.5-183.5 us, DRAM 82.3-82.8%, traffic at the compulsory minimum
// ~1.18 GB = 1.024 GB writes + 128 MB indices + ~87 MB deduped gather).
//
//  - One warp per row (C=64): every STG.128 instruction writes 512 fully
//    contiguous ascending bytes; 4 stores cover the row's 2048-B span.
//  - __stcs on the write-once output (full-line-per-instruction pattern).
//  - __ldcs on the read-once indices / nempty_idx streams; __ldg on the
//    gathered data rows (~32% duplication -> keep L2-cached).
//  - Flat launch, block=256 (sweep: 128 neutral, 512 -1%).
//
// Measured dead ends (do not reintroduce):
//  R2: partial-line store instructions + .cs  -> +50% DRAM write traffic
//  R5: 4-rows-per-warp batching               -> L1tex queue serialization
//  R7: persistent grid-stride                 -> per-row dependent chain
//  R9: block=512                              -> occupancy quantization
// Analyzed dead ends: memset+sparse-scatter (adds traffic), TMA stores
// (LTS cap path-independent), wider stores (issue=16.6%, not binding).

#define NUM_CHILDREN 8

__device__ __forceinline__ float4 child_select(int4 ix, float4 d, int c) {
    float4 o;
    o.x = (ix.x == c) ? d.x : 0.0f;
    o.y = (ix.y == c) ? d.y : 0.0f;
    o.z = (ix.z == c) ? d.z : 0.0f;
    o.w = (ix.w == c) ? d.w : 0.0f;
    return o;
}

// C = 64 fast path: one warp per row.
__global__ void __launch_bounds__(256)
octree_unpool_warprow_kernel(const float4* __restrict__ data,
                             const int4*  __restrict__ indices,
                             const int*   __restrict__ nempty_idx,
                             float4*      __restrict__ out,
                             int num)
{
    constexpr int C4 = 16;                       // float4 lanes per row
    int gtid = blockIdx.x * blockDim.x + threadIdx.x;
    int i    = gtid >> 5;                        // row = warp id
    int t    = gtid & 31;                        // lane in warp
    if (i >= num) return;

    int l = t & 15;                              // float4 lane within row
    int h = t >> 4;                              // half-warp id (0/1)

    int src = __ldcs(&nempty_idx[i]);            // read-once: evict-first
    float4 d  = __ldg(&data[(long long)src * C4 + l]);      // reused: cached
    int4   ix = __ldcs(&indices[(long long)i * C4 + l]);    // read-once

    float4* rowbase = out + (long long)i * (NUM_CHILDREN * C4);
#pragma unroll
    for (int j = 0; j < 4; j++) {
        int c = h + 2 * j;                       // child slot this thread writes
        // position within row = c*16 + l = t + 32*j  (ascending contiguous)
        __stcs(rowbase + t + 32 * j, child_select(ix, d, c));
    }
}

// Generic-C vectorized kernel (runtime C4) for C % 4 == 0 but C != 64.
__global__ void __launch_bounds__(256)
octree_unpool_vec_dyn_kernel(const float4* __restrict__ data,
                             const int4*  __restrict__ indices,
                             const int*   __restrict__ nempty_idx,
                             float4*      __restrict__ out,
                             int num, int C4)
{
    int gtid = blockIdx.x * blockDim.x + threadIdx.x;
    int i    = gtid / C4;
    int lane = gtid - i * C4;
    if (i >= num) return;

    int src = __ldcs(&nempty_idx[i]);
    float4 d  = __ldg(&data[(long long)src * C4 + lane]);
    int4   ix = __ldcs(&indices[(long long)i * C4 + lane]);

    long long base = (long long)i * (NUM_CHILDREN * C4) + lane;
#pragma unroll
    for (int c = 0; c < NUM_CHILDREN; c++) {
        out[base + (long long)c * C4] = child_select(ix, d, c);
    }
}

// Scalar fallback for arbitrary C.
__global__ void __launch_bounds__(256)
octree_unpool_scalar_kernel(const float* __restrict__ data,
                            const int*   __restrict__ indices,
                            const int*   __restrict__ nempty_idx,
                            float*       __restrict__ out,
                            int num, int C)
{
    long long gtid = (long long)blockIdx.x * blockDim.x + threadIdx.x;
    long long total = (long long)num * C;
    if (gtid >= total) return;
    int i = (int)(gtid / C);
    int k = (int)(gtid - (long long)i * C);

    int src  = __ldcs(&nempty_idx[i]);
    float dv = __ldg(&data[(long long)src * C + k]);
    int   ix = __ldcs(&indices[(long long)i * C + k]);

    long long base = ((long long)i * NUM_CHILDREN) * C + k;
#pragma unroll
    for (int c = 0; c < NUM_CHILDREN; c++) {
        out[base + (long long)c * C] = (ix == c) ? dv : 0.0f;
    }
}

extern "C" void kernel_launch(void* const* d_in, const int* in_sizes, int n_in,
                              void* d_out, int out_size)
{
    const float* data       = (const float*)d_in[0];
    const int*   indices    = (const int*)d_in[1];
    const int*   nempty_idx = (const int*)d_in[2];
    // d_in[3] = depth (unused: the gather is already expressed by nempty_idx)

    float* out = (float*)d_out;

    int num = in_sizes[2];
    int C   = (num > 0) ? (in_sizes[1] / num) : 0;

    if (num <= 0 || C <= 0) return;

    if (C == 64) {
        long long threads = (long long)num * 32;   // one warp per row
        int block = 256;
        int grid  = (int)((threads + block - 1) / block);
        octree_unpool_warprow_kernel<<<grid, block>>>(
            (const float4*)data, (const int4*)indices, nempty_idx,
            (float4*)out, num);
    } else if ((C & 3) == 0) {
        int C4 = C >> 2;
        long long threads = (long long)num * C4;
        int block = 256;
        int grid  = (int)((threads + block - 1) / block);
        octree_unpool_vec_dyn_kernel<<<grid, block>>>(
            (const float4*)data, (const int4*)indices, nempty_idx,
            (float4*)out, num, C4);
    } else {
        long long threads = (long long)num * C;
        int block = 256;
        int grid  = (int)((threads + block - 1) / block);
        octree_unpool_scalar_kernel<<<grid, block>>>(
            data, indices, nempty_idx, out, num, C);
    }
}

// round 14
// speedup vs baseline: 1.0035x; 1.0014x over previous
#include <cuda_runtime.h>
#include <cuda_bf16.h>
#include <cstdint>

// OctreeMaxUnpool:
//   out[(i*8 + c)*C + k] = (indices[i*C + k] == c) ? data[nempty_idx[i]*C + k] : 0
//
// R14 = converged-optimum kernel (182.5-183.5 us, DRAM 82.2-82.8%,
// compulsory-minimum traffic) with the final untried cache-policy point:
// __stwt (write-through) on the write-once output instead of __stcs.
// Rationale: bypass L2 write-allocation entirely for the 1.024 GB output
// stream; warp-wide store instructions already cover full 128-B lines so
// instruction-level combining is preserved. Everything else frozen:
// one warp per row, block=256, __ldcs read-once streams, __ldg cached gather.

#define NUM_CHILDREN 8

__device__ __forceinline__ float4 child_select(int4 ix, float4 d, int c) {
    float4 o;
    o.x = (ix.x == c) ? d.x : 0.0f;
    o.y = (ix.y == c) ? d.y : 0.0f;
    o.z = (ix.z == c) ? d.z : 0.0f;
    o.w = (ix.w == c) ? d.w : 0.0f;
    return o;
}

// C = 64 fast path: one warp per row.
__global__ void __launch_bounds__(256)
octree_unpool_warprow_kernel(const float4* __restrict__ data,
                             const int4*  __restrict__ indices,
                             const int*   __restrict__ nempty_idx,
                             float4*      __restrict__ out,
                             int num)
{
    constexpr int C4 = 16;                       // float4 lanes per row
    int gtid = blockIdx.x * blockDim.x + threadIdx.x;
    int i    = gtid >> 5;                        // row = warp id
    int t    = gtid & 31;                        // lane in warp
    if (i >= num) return;

    int l = t & 15;                              // float4 lane within row
    int h = t >> 4;                              // half-warp id (0/1)

    int src = __ldcs(&nempty_idx[i]);            // read-once: evict-first
    float4 d  = __ldg(&data[(long long)src * C4 + l]);      // reused: cached
    int4   ix = __ldcs(&indices[(long long)i * C4 + l]);    // read-once

    float4* rowbase = out + (long long)i * (NUM_CHILDREN * C4);
#pragma unroll
    for (int j = 0; j < 4; j++) {
        int c = h + 2 * j;                       // child slot this thread writes
        // position within row = c*16 + l = t + 32*j  (ascending contiguous)
        __stwt(rowbase + t + 32 * j, child_select(ix, d, c));
    }
}

// Generic-C vectorized kernel (runtime C4) for C % 4 == 0 but C != 64.
__global__ void __launch_bounds__(256)
octree_unpool_vec_dyn_kernel(const float4* __restrict__ data,
                             const int4*  __restrict__ indices,
                             const int*   __restrict__ nempty_idx,
                             float4*      __restrict__ out,
                             int num, int C4)
{
    int gtid = blockIdx.x * blockDim.x + threadIdx.x;
    int i    = gtid / C4;
    int lane = gtid - i * C4;
    if (i >= num) return;

    int src = __ldcs(&nempty_idx[i]);
    float4 d  = __ldg(&data[(long long)src * C4 + lane]);
    int4   ix = __ldcs(&indices[(long long)i * C4 + lane]);

    long long base = (long long)i * (NUM_CHILDREN * C4) + lane;
#pragma unroll
    for (int c = 0; c < NUM_CHILDREN; c++) {
        out[base + (long long)c * C4] = child_select(ix, d, c);
    }
}

// Scalar fallback for arbitrary C.
__global__ void __launch_bounds__(256)
octree_unpool_scalar_kernel(const float* __restrict__ data,
                            const int*   __restrict__ indices,
                            const int*   __restrict__ nempty_idx,
                            float*       __restrict__ out,
                            int num, int C)
{
    long long gtid = (long long)blockIdx.x * blockDim.x + threadIdx.x;
    long long total = (long long)num * C;
    if (gtid >= total) return;
    int i = (int)(gtid / C);
    int k = (int)(gtid - (long long)i * C);

    int src  = __ldcs(&nempty_idx[i]);
    float dv = __ldg(&data[(long long)src * C + k]);
    int   ix = __ldcs(&indices[(long long)i * C + k]);

    long long base = ((long long)i * NUM_CHILDREN) * C + k;
#pragma unroll
    for (int c = 0; c < NUM_CHILDREN; c++) {
        out[base + (long long)c * C] = (ix == c) ? dv : 0.0f;
    }
}

extern "C" void kernel_launch(void* const* d_in, const int* in_sizes, int n_in,
                              void* d_out, int out_size)
{
    const float* data       = (const float*)d_in[0];
    const int*   indices    = (const int*)d_in[1];
    const int*   nempty_idx = (const int*)d_in[2];
    // d_in[3] = depth (unused: the gather is already expressed by nempty_idx)

    float* out = (float*)d_out;

    int num = in_sizes[2];
    int C   = (num > 0) ? (in_sizes[1] / num) : 0;

    if (num <= 0 || C <= 0) return;

    if (C == 64) {
        long long threads = (long long)num * 32;   // one warp per row
        int block = 256;
        int grid  = (int)((threads + block - 1) / block);
        octree_unpool_warprow_kernel<<<grid, block>>>(
            (const float4*)data, (const int4*)indices, nempty_idx,
            (float4*)out, num);
    } else if ((C & 3) == 0) {
        int C4 = C >> 2;
        long long threads = (long long)num * C4;
        int block = 256;
        int grid  = (int)((threads + block - 1) / block);
        octree_unpool_vec_dyn_kernel<<<grid, block>>>(
            (const float4*)data, (const int4*)indices, nempty_idx,
            (float4*)out, num, C4);
    } else {
        long long threads = (long long)num * C;
        int block = 256;
        int grid  = (int)((threads + block - 1) / block);
        octree_unpool_scalar_kernel<<<grid, block>>>(
            data, indices, nempty_idx, out, num, C);
    }
}

// round 15
// speedup vs baseline: 1.0053x; 1.0018x over previous
#include <cuda_runtime.h>
#include <cuda_bf16.h>
#include <cstdint>

// OctreeMaxUnpool:
//   out[(i*8 + c)*C + k] = (indices[i*C + k] == c) ? data[nempty_idx[i]*C + k] : 0
//
// FINAL kernel — verified optimum across a 14-round sweep:
//   182.5-183.5 us, DRAM 82.2-82.8%, HBM ~6.55 TB/s, traffic at the
//   compulsory minimum (~1.18 GB = 1.024 GB writes + 128 MB indices
//   + ~87 MB L2-deduped gather reads).
//
// Design (every element measured against alternatives):
//  - One warp per row (C=64): every STG.128 instruction writes 512 fully
//    contiguous ascending bytes; 4 stores cover the row's 2048-B span.
//  - __stcs on the write-once output (ties __stwt/default; keeps L2 for
//    the reused data rows).
//  - __ldcs on read-once indices / nempty_idx; __ldg on gathered data rows
//    (~32% duplication, sorted gather -> high L2 dedup, L2=49%).
//  - Flat launch, block=256 (sweep: 128 neutral, 512 -1%).
//
// Measured dead ends (do not reintroduce):
//  - partial-line store instructions + .cs  -> +50% DRAM write traffic (389us)
//  - 4-rows-per-warp batching               -> L1tex queue serialization (201us)
//  - persistent grid-stride                 -> per-row dependent chain (213us)
// Analyzed dead ends: memset+sparse-scatter (adds traffic), TMA stores
// (LTS cap path-independent), wider stores (issue=16.6%, not binding).

#define NUM_CHILDREN 8

__device__ __forceinline__ float4 child_select(int4 ix, float4 d, int c) {
    float4 o;
    o.x = (ix.x == c) ? d.x : 0.0f;
    o.y = (ix.y == c) ? d.y : 0.0f;
    o.z = (ix.z == c) ? d.z : 0.0f;
    o.w = (ix.w == c) ? d.w : 0.0f;
    return o;
}

// C = 64 fast path: one warp per row.
__global__ void __launch_bounds__(256)
octree_unpool_warprow_kernel(const float4* __restrict__ data,
                             const int4*  __restrict__ indices,
                             const int*   __restrict__ nempty_idx,
                             float4*      __restrict__ out,
                             int num)
{
    constexpr int C4 = 16;                       // float4 lanes per row
    int gtid = blockIdx.x * blockDim.x + threadIdx.x;
    int i    = gtid >> 5;                        // row = warp id
    int t    = gtid & 31;                        // lane in warp
    if (i >= num) return;

    int l = t & 15;                              // float4 lane within row
    int h = t >> 4;                              // half-warp id (0/1)

    int src = __ldcs(&nempty_idx[i]);            // read-once: evict-first
    float4 d  = __ldg(&data[(long long)src * C4 + l]);      // reused: cached
    int4   ix = __ldcs(&indices[(long long)i * C4 + l]);    // read-once

    float4* rowbase = out + (long long)i * (NUM_CHILDREN * C4);
#pragma unroll
    for (int j = 0; j < 4; j++) {
        int c = h + 2 * j;                       // child slot this thread writes
        // position within row = c*16 + l = t + 32*j  (ascending contiguous)
        __stcs(rowbase + t + 32 * j, child_select(ix, d, c));
    }
}

// Generic-C vectorized kernel (runtime C4) for C % 4 == 0 but C != 64.
__global__ void __launch_bounds__(256)
octree_unpool_vec_dyn_kernel(const float4* __restrict__ data,
                             const int4*  __restrict__ indices,
                             const int*   __restrict__ nempty_idx,
                             float4*      __restrict__ out,
                             int num, int C4)
{
    int gtid = blockIdx.x * blockDim.x + threadIdx.x;
    int i    = gtid / C4;
    int lane = gtid - i * C4;
    if (i >= num) return;

    int src = __ldcs(&nempty_idx[i]);
    float4 d  = __ldg(&data[(long long)src * C4 + lane]);
    int4   ix = __ldcs(&indices[(long long)i * C4 + lane]);

    long long base = (long long)i * (NUM_CHILDREN * C4) + lane;
#pragma unroll
    for (int c = 0; c < NUM_CHILDREN; c++) {
        out[base + (long long)c * C4] = child_select(ix, d, c);
    }
}

// Scalar fallback for arbitrary C.
__global__ void __launch_bounds__(256)
octree_unpool_scalar_kernel(const float* __restrict__ data,
                            const int*   __restrict__ indices,
                            const int*   __restrict__ nempty_idx,
                            float*       __restrict__ out,
                            int num, int C)
{
    long long gtid = (long long)blockIdx.x * blockDim.x + threadIdx.x;
    long long total = (long long)num * C;
    if (gtid >= total) return;
    int i = (int)(gtid / C);
    int k = (int)(gtid - (long long)i * C);

    int src  = __ldcs(&nempty_idx[i]);
    float dv = __ldg(&data[(long long)src * C + k]);
    int   ix = __ldcs(&indices[(long long)i * C + k]);

    long long base = ((long long)i * NUM_CHILDREN) * C + k;
#pragma unroll
    for (int c = 0; c < NUM_CHILDREN; c++) {
        out[base + (long long)c * C] = (ix == c) ? dv : 0.0f;
    }
}

extern "C" void kernel_launch(void* const* d_in, const int* in_sizes, int n_in,
                              void* d_out, int out_size)
{
    const float* data       = (const float*)d_in[0];
    const int*   indices    = (const int*)d_in[1];
    const int*   nempty_idx = (const int*)d_in[2];
    // d_in[3] = depth (unused: the gather is already expressed by nempty_idx)

    float* out = (float*)d_out;

    int num = in_sizes[2];
    int C   = (num > 0) ? (in_sizes[1] / num) : 0;

    if (num <= 0 || C <= 0) return;

    if (C == 64) {
        long long threads = (long long)num * 32;   // one warp per row
        int block = 256;
        int grid  = (int)((threads + block - 1) / block);
        octree_unpool_warprow_kernel<<<grid, block>>>(
            (const float4*)data, (const int4*)indices, nempty_idx,
            (float4*)out, num);
    } else if ((C & 3) == 0) {
        int C4 = C >> 2;
        long long threads = (long long)num * C4;
        int block = 256;
        int grid  = (int)((threads + block - 1) / block);
        octree_unpool_vec_dyn_kernel<<<grid, block>>>(
            (const float4*)data, (const int4*)indices, nempty_idx,
            (float4*)out, num, C4);
    } else {
        long long threads = (long long)num * C;
        int block = 256;
        int grid  = (int)((threads + block - 1) / block);
        octree_unpool_scalar_kernel<<<grid, block>>>(
            data, indices, nempty_idx, out, num, C);
    }
}